// round 16
// baseline (speedup 1.0000x reference)
#include <cuda_runtime.h>
#include <cuda_bf16.h>
#include <cuda_fp16.h>
#include <cstdint>

#define D 128
#define NMAX 50000
#define NPAD 50176          // 49 * 1024
#define EMAX 600000
#define NBLK 49             // scan blocks of 1024

// ---------------------------------------------------------------------------
// Scratch (__device__ globals per allocation rules)
// ---------------------------------------------------------------------------
__device__ __align__(16) __half        g_f16[NPAD * D];   // fp16 copy of feat (gather source)
__device__ __align__(16) __nv_bfloat16 g_hA[NPAD * D];    // (feat+agg) hi; pad rows stay 0
__device__ __align__(16) __nv_bfloat16 g_hB[NPAD * D];    // (feat+agg) lo
__device__ __align__(16) __nv_bfloat16 g_w1tH[D * D];     // W1^T hi [col][k]
__device__ __align__(16) __nv_bfloat16 g_w1tL[D * D];     // W1^T lo
__device__ __align__(16) __nv_bfloat16 g_w2tH[D * D];     // W2^T hi
__device__ __align__(16) __nv_bfloat16 g_w2tL[D * D];     // W2^T lo
__device__ __align__(16) float         g_stats[2 * D];    // col sum/sumsq
__device__ int g_cnt[NPAD];        // per-dst edge counts
__device__ int g_off[NPAD + 1];    // CSR offsets
__device__ int g_cur[NPAD];        // scatter cursors
__device__ int g_srcs[EMAX];       // edge sources grouped by dst
__device__ int g_bsum[NBLK];       // per-block count sums

// ---------------------------------------------------------------------------
// PTX helpers (portable ISA only — tcgen05 unavailable on compute_103 target)
// ---------------------------------------------------------------------------
__device__ __forceinline__ void cp16(uint32_t dst, const void* src) {
    asm volatile("cp.async.cg.shared.global [%0], [%1], 16;" :: "r"(dst), "l"(src));
}
__device__ __forceinline__ void cp_commit() { asm volatile("cp.async.commit_group;"); }
template <int N>
__device__ __forceinline__ void cp_wait() {
    asm volatile("cp.async.wait_group %0;" :: "n"(N));
}
__device__ __forceinline__ uint32_t smem_u32(const void* p) {
    return (uint32_t)__cvta_generic_to_shared(p);
}
__device__ __forceinline__ void mma16816(float* c, const uint32_t* a, const uint32_t* b) {
    asm volatile(
        "mma.sync.aligned.m16n8k16.row.col.f32.bf16.bf16.f32 "
        "{%0,%1,%2,%3}, {%4,%5,%6,%7}, {%8,%9}, {%0,%1,%2,%3};"
        : "+f"(c[0]), "+f"(c[1]), "+f"(c[2]), "+f"(c[3])
        : "r"(a[0]), "r"(a[1]), "r"(a[2]), "r"(a[3]), "r"(b[0]), "r"(b[1]));
}
__device__ __forceinline__ void ldsm4(uint32_t* r, uint32_t addr) {
    asm volatile("ldmatrix.sync.aligned.m8n8.x4.shared.b16 {%0,%1,%2,%3}, [%4];"
                 : "=r"(r[0]), "=r"(r[1]), "=r"(r[2]), "=r"(r[3]) : "r"(addr));
}

// Padded row stride 136 halves (272 B): conflict-free ldmatrix/STS.
#define SH 136
#define TILE_B (128 * SH * 2)            // 34816 B : one weight tile (hi or lo)
#define TILE_A (64 * SH * 2)             // 17408 B : one A or Y tile (hi or lo)
#define OFF_A   (4 * TILE_B)             // A hi/lo
#define OFF_Y   (OFF_A + 2 * TILE_A)     // Y hi/lo (separate buffer)
#define OFF_BIAS (OFF_Y + 2 * TILE_A)
#define SMEM_FUSED (OFF_BIAS + 1024)     // 209920 B -> 1 CTA/SM

// ---------------------------------------------------------------------------
// Kernel 1: zero counts/stats, split weights, AND convert feat -> fp16.
// Grid sized for n4 = N*D/4 (largest of the jobs).
// ---------------------------------------------------------------------------
__global__ void k_init(const float* __restrict__ W1, const float* __restrict__ W2,
                       const float4* __restrict__ feat, int n4) {
    int i = blockIdx.x * blockDim.x + threadIdx.x;
    if (i < NPAD) g_cnt[i] = 0;
    if (i < 2 * D) g_stats[i] = 0.0f;
    if (i < D * D) {
        int k = i >> 7, c = i & 127;
        float w1 = W1[i], w2 = W2[i];
        __nv_bfloat16 h1 = __float2bfloat16(w1);
        __nv_bfloat16 h2 = __float2bfloat16(w2);
        g_w1tH[c * D + k] = h1;
        g_w1tL[c * D + k] = __float2bfloat16(w1 - __bfloat162float(h1));
        g_w2tH[c * D + k] = h2;
        g_w2tL[c * D + k] = __float2bfloat16(w2 - __bfloat162float(h2));
    }
    if (i < n4) {
        float4 v = feat[i];
        __half2 p01 = __floats2half2_rn(v.x, v.y);
        __half2 p23 = __floats2half2_rn(v.z, v.w);
        uint2 pk;
        pk.x = *reinterpret_cast<uint32_t*>(&p01);
        pk.y = *reinterpret_cast<uint32_t*>(&p23);
        reinterpret_cast<uint2*>(g_f16)[i] = pk;
    }
}

// ---------------------------------------------------------------------------
// Kernel 2: histogram of edge destinations — 4 edges/thread (MLP=4)
// ---------------------------------------------------------------------------
__global__ void k_hist(const int* __restrict__ ei, int E) {
    int i4 = blockIdx.x * blockDim.x + threadIdx.x;
    int e4 = E >> 2;
    if (i4 < e4) {
        int4 d = reinterpret_cast<const int4*>(ei + E)[i4];
        atomicAdd(&g_cnt[d.x], 1);
        atomicAdd(&g_cnt[d.y], 1);
        atomicAdd(&g_cnt[d.z], 1);
        atomicAdd(&g_cnt[d.w], 1);
    }
    int tail = e4 * 4 + i4;
    if (i4 < (E & 3)) atomicAdd(&g_cnt[ei[E + tail]], 1);
}

// ---------------------------------------------------------------------------
// Kernel 3: per-block (1024 counts) reduction -> g_bsum
// ---------------------------------------------------------------------------
__global__ void k_bsum() {
    __shared__ int s[32];
    int t = threadIdx.x;
    int v = g_cnt[blockIdx.x * 1024 + t];
#pragma unroll
    for (int off = 16; off > 0; off >>= 1) v += __shfl_xor_sync(0xFFFFFFFFu, v, off);
    if ((t & 31) == 0) s[t >> 5] = v;
    __syncthreads();
    if (t < 32) {
        int w = s[t];
#pragma unroll
        for (int off = 16; off > 0; off >>= 1) w += __shfl_xor_sync(0xFFFFFFFFu, w, off);
        if (t == 0) g_bsum[blockIdx.x] = w;
    }
}

// ---------------------------------------------------------------------------
// Kernel 4: per-block scan via two-level shfl; race-free block base (warp 1)
// ---------------------------------------------------------------------------
__global__ void k_off() {
    __shared__ int s_wsum[32];
    __shared__ int s_base;
    const int t = threadIdx.x;
    const int lane = t & 31;
    const int w = t >> 5;
    const int gi = blockIdx.x * 1024 + t;
    const int c = g_cnt[gi];

    int v = c;
#pragma unroll
    for (int off = 1; off < 32; off <<= 1) {
        int u = __shfl_up_sync(0xFFFFFFFFu, v, off);
        if (lane >= off) v += u;
    }
    if (lane == 31) s_wsum[w] = v;

    if (w == 1) {
        int b = 0;
        if (lane < blockIdx.x) b = g_bsum[lane];
        if (lane + 32 < blockIdx.x) b += g_bsum[lane + 32];
#pragma unroll
        for (int off = 16; off > 0; off >>= 1) b += __shfl_xor_sync(0xFFFFFFFFu, b, off);
        if (lane == 0) s_base = b;
    }
    __syncthreads();

    if (w == 0) {
        int x = s_wsum[lane];
#pragma unroll
        for (int off = 1; off < 32; off <<= 1) {
            int u = __shfl_up_sync(0xFFFFFFFFu, x, off);
            if (lane >= off) x += u;
        }
        s_wsum[lane] = x;
    }
    __syncthreads();

    const int base = s_base;
    const int incl = v + (w ? s_wsum[w - 1] : 0);
    const int excl = base + incl - c;
    g_off[gi] = excl;
    g_cur[gi] = excl;
    if (gi == NPAD - 1) g_off[NPAD] = base + s_wsum[31];
}

// ---------------------------------------------------------------------------
// Kernel 5: reorder edge sources into CSR order — 4 edges/thread (MLP=4)
// ---------------------------------------------------------------------------
__global__ void k_reorder(const int* __restrict__ ei, int E) {
    int i4 = blockIdx.x * blockDim.x + threadIdx.x;
    int e4 = E >> 2;
    if (i4 < e4) {
        int4 s = reinterpret_cast<const int4*>(ei)[i4];
        int4 d = reinterpret_cast<const int4*>(ei + E)[i4];
        int p0 = atomicAdd(&g_cur[d.x], 1);
        int p1 = atomicAdd(&g_cur[d.y], 1);
        int p2 = atomicAdd(&g_cur[d.z], 1);
        int p3 = atomicAdd(&g_cur[d.w], 1);
        g_srcs[p0] = s.x;
        g_srcs[p1] = s.y;
        g_srcs[p2] = s.z;
        g_srcs[p3] = s.w;
    }
    int tail = e4 * 4 + i4;
    if (i4 < (E & 3)) {
        int src = ei[tail];
        int dst = ei[E + tail];
        int pos = atomicAdd(&g_cur[dst], 1);
        g_srcs[pos] = src;
    }
}

// ---------------------------------------------------------------------------
// Kernel 6: gather-sum (fp16 neighbors, f32 accum & self) + bf16 hi/lo split.
// One warp/node; lane owns 4 columns. Gather traffic halved vs f32.
// ---------------------------------------------------------------------------
__global__ void k_agg(const float* __restrict__ feat, int N) {
    int node = (blockIdx.x * blockDim.x + threadIdx.x) >> 5;
    int lane = threadIdx.x & 31;
    if (node >= N) return;
    int j = g_off[node];
    const int end = g_off[node + 1];
    // self term from exact f32 feat
    float4 acc = reinterpret_cast<const float4*>(feat)[(size_t)node * 32 + lane];
    const uint2* f16 = reinterpret_cast<const uint2*>(g_f16);
    for (; j + 3 < end; j += 4) {
        int s0 = g_srcs[j], s1 = g_srcs[j + 1], s2 = g_srcs[j + 2], s3 = g_srcs[j + 3];
        uint2 v0 = f16[(size_t)s0 * 32 + lane];
        uint2 v1 = f16[(size_t)s1 * 32 + lane];
        uint2 v2 = f16[(size_t)s2 * 32 + lane];
        uint2 v3 = f16[(size_t)s3 * 32 + lane];
#pragma unroll
        for (int e = 0; e < 4; ++e) {
            uint2 vv = (e == 0) ? v0 : (e == 1) ? v1 : (e == 2) ? v2 : v3;
            float2 a = __half22float2(*reinterpret_cast<__half2*>(&vv.x));
            float2 b = __half22float2(*reinterpret_cast<__half2*>(&vv.y));
            acc.x += a.x; acc.y += a.y; acc.z += b.x; acc.w += b.y;
        }
    }
    for (; j < end; ++j) {
        uint2 vv = f16[(size_t)g_srcs[j] * 32 + lane];
        float2 a = __half22float2(*reinterpret_cast<__half2*>(&vv.x));
        float2 b = __half22float2(*reinterpret_cast<__half2*>(&vv.y));
        acc.x += a.x; acc.y += a.y; acc.z += b.x; acc.w += b.y;
    }
    __nv_bfloat162 h01 = __floats2bfloat162_rn(acc.x, acc.y);
    __nv_bfloat162 h23 = __floats2bfloat162_rn(acc.z, acc.w);
    __nv_bfloat162 l01 = __floats2bfloat162_rn(acc.x - __bfloat162float(h01.x),
                                               acc.y - __bfloat162float(h01.y));
    __nv_bfloat162 l23 = __floats2bfloat162_rn(acc.z - __bfloat162float(h23.x),
                                               acc.w - __bfloat162float(h23.y));
    uint2 hv, lv;
    hv.x = *reinterpret_cast<uint32_t*>(&h01);
    hv.y = *reinterpret_cast<uint32_t*>(&h23);
    lv.x = *reinterpret_cast<uint32_t*>(&l01);
    lv.y = *reinterpret_cast<uint32_t*>(&l23);
    reinterpret_cast<uint2*>(g_hA)[(size_t)node * 32 + lane] = hv;
    reinterpret_cast<uint2*>(g_hB)[(size_t)node * 32 + lane] = lv;
}

// ---------------------------------------------------------------------------
// Kernel 7: persistent fused MLP, 512 threads (16 warps), 64-row tiles.
// (Exact R13 configuration — best measured.)
// ---------------------------------------------------------------------------
__global__ __launch_bounds__(512, 1)
void k_fused(const float* __restrict__ b1, const float* __restrict__ b2,
             float* __restrict__ outF, int M, int nTiles) {
    extern __shared__ __align__(16) uint8_t smem[];
    const uint32_t sBase = smem_u32(smem);
    uint16_t* sYh = reinterpret_cast<uint16_t*>(smem + OFF_Y);
    uint16_t* sYl = reinterpret_cast<uint16_t*>(smem + OFF_Y + TILE_A);
    float* s_b1 = reinterpret_cast<float*>(smem + OFF_BIAS);
    float* s_b2 = s_b1 + D;

    const int tid = threadIdx.x;
    const int wid = tid >> 5;
    const int lane = tid & 31;
    const int g = lane >> 2;
    const int l4 = lane & 3;
    const int warpM = wid & 3;
    const int warpN = wid >> 2;

    if (tid < D) s_b1[tid] = b1[tid];
    else if (tid < 2 * D) s_b2[tid - D] = b2[tid - D];

#pragma unroll
    for (int t = 0; t < 4; ++t) {
        int idx = tid + t * 512;
        int row = idx >> 4;
        int kb = (idx & 15) * 16;
        uint32_t dOff = (uint32_t)(row * (SH * 2) + kb);
        size_t gOff = (size_t)row * 256 + kb;
        cp16(sBase + dOff,              (const uint8_t*)g_w1tH + gOff);
        cp16(sBase + TILE_B + dOff,     (const uint8_t*)g_w1tL + gOff);
        cp16(sBase + 2 * TILE_B + dOff, (const uint8_t*)g_w2tH + gOff);
        cp16(sBase + 3 * TILE_B + dOff, (const uint8_t*)g_w2tL + gOff);
    }
    cp_commit();

    auto issueA = [&](int tile) {
        const int rowBase = tile * 64;
#pragma unroll
        for (int tt = 0; tt < 4; ++tt) {
            int idx = tid + tt * 512;
            int hl = idx >> 10;
            int row = (idx >> 4) & 63;
            int kb = (idx & 15) * 16;
            uint32_t dOff = (uint32_t)(OFF_A + hl * TILE_A + row * (SH * 2) + kb);
            size_t gOff = (size_t)(rowBase + row) * 256 + kb;
            cp16(sBase + dOff, (const uint8_t*)(hl ? g_hB : g_hA) + gOff);
        }
        cp_commit();
    };

    const int arow = warpM * 16 + (lane & 7) + ((lane >> 3) & 1) * 8;
    const uint32_t aOff = (uint32_t)((arow * SH + (lane >> 4) * 8) * 2);
    uint32_t bOff[2];
#pragma unroll
    for (int pr = 0; pr < 2; ++pr) {
        int brow = warpN * 32 + pr * 16 + (lane & 7) + (lane >> 4) * 8;
        int bkoff = ((lane >> 3) & 1) * 8;
        bOff[pr] = (uint32_t)((brow * SH + bkoff) * 2);
    }

    float cs[4][2], cq[4][2];
#pragma unroll
    for (int ni = 0; ni < 4; ++ni) {
        cs[ni][0] = cs[ni][1] = 0.f;
        cq[ni][0] = cq[ni][1] = 0.f;
    }

    float c[4][4];

    auto runGemm = [&](uint32_t aHi, uint32_t aLo, uint32_t bHi, uint32_t bLo) {
#pragma unroll
        for (int ni = 0; ni < 4; ++ni)
#pragma unroll
            for (int e = 0; e < 4; ++e) c[ni][e] = 0.f;
#pragma unroll
        for (int pass = 0; pass < 3; ++pass) {
            const uint32_t aBase = (pass == 2 ? aLo : aHi);
            const uint32_t bBase = (pass == 1 ? bLo : bHi);
#pragma unroll
            for (int ks = 0; ks < 8; ++ks) {
                uint32_t a[4], b[2][4];
                ldsm4(a, aBase + aOff + ks * 32);
                ldsm4(b[0], bBase + bOff[0] + ks * 32);
                ldsm4(b[1], bBase + bOff[1] + ks * 32);
                mma16816(c[0], a, &b[0][0]);
                mma16816(c[1], a, &b[0][2]);
                mma16816(c[2], a, &b[1][0]);
                mma16816(c[3], a, &b[1][2]);
            }
        }
    };

    int t = blockIdx.x;
    if (t < nTiles) issueA(t);

    for (; t < nTiles; t += gridDim.x) {
        const int rowBase = t * 64;
        const int tNext = t + gridDim.x;

        cp_wait<0>();
        __syncthreads();

        runGemm(sBase + OFF_A, sBase + OFF_A + TILE_A, sBase, sBase + TILE_B);
        __syncthreads();

        if (tNext < nTiles) issueA(tNext);

#pragma unroll
        for (int half = 0; half < 2; ++half) {
            const int lrow = warpM * 16 + g + half * 8;
#pragma unroll
            for (int ni = 0; ni < 4; ++ni) {
                const int col = warpN * 32 + ni * 8 + 2 * l4;
                float v0 = fmaxf(c[ni][half * 2 + 0] + s_b1[col], 0.f);
                float v1 = fmaxf(c[ni][half * 2 + 1] + s_b1[col + 1], 0.f);
                __nv_bfloat16 h0 = __float2bfloat16(v0);
                __nv_bfloat16 h1 = __float2bfloat16(v1);
                __nv_bfloat162 hh; hh.x = h0; hh.y = h1;
                __nv_bfloat162 ll = __floats2bfloat162_rn(
                    v0 - __bfloat162float(h0), v1 - __bfloat162float(h1));
                *reinterpret_cast<uint32_t*>(&sYh[lrow * SH + col]) =
                    *reinterpret_cast<uint32_t*>(&hh);
                *reinterpret_cast<uint32_t*>(&sYl[lrow * SH + col]) =
                    *reinterpret_cast<uint32_t*>(&ll);
            }
        }
        __syncthreads();

        runGemm(sBase + OFF_Y, sBase + OFF_Y + TILE_A,
                sBase + 2 * TILE_B, sBase + 3 * TILE_B);

#pragma unroll
        for (int half = 0; half < 2; ++half) {
            const int row = rowBase + warpM * 16 + g + half * 8;
            if (row < M) {
#pragma unroll
                for (int ni = 0; ni < 4; ++ni) {
                    const int col = warpN * 32 + ni * 8 + 2 * l4;
                    float v0 = fmaxf(c[ni][half * 2 + 0] + s_b2[col], 0.f);
                    float v1 = fmaxf(c[ni][half * 2 + 1] + s_b2[col + 1], 0.f);
                    float2 st; st.x = v0; st.y = v1;
                    *reinterpret_cast<float2*>(outF + (size_t)row * D + col) = st;
                    cs[ni][0] += v0; cs[ni][1] += v1;
                    cq[ni][0] += v0 * v0; cq[ni][1] += v1 * v1;
                }
            }
        }
    }

    // ---- Final BN stats reduction ----
#pragma unroll
    for (int off = 4; off < 32; off <<= 1) {
#pragma unroll
        for (int ni = 0; ni < 4; ++ni) {
#pragma unroll
            for (int e = 0; e < 2; ++e) {
                cs[ni][e] += __shfl_xor_sync(0xFFFFFFFFu, cs[ni][e], off);
                cq[ni][e] += __shfl_xor_sync(0xFFFFFFFFu, cq[ni][e], off);
            }
        }
    }
    __syncthreads();
    float* redS = reinterpret_cast<float*>(smem + OFF_A);
    float* redQ = redS + 512;
    if (g == 0) {
#pragma unroll
        for (int ni = 0; ni < 4; ++ni) {
#pragma unroll
            for (int e = 0; e < 2; ++e) {
                int cc = ni * 8 + 2 * l4 + e;
                redS[wid * 32 + cc] = cs[ni][e];
                redQ[wid * 32 + cc] = cq[ni][e];
            }
        }
    }
    __syncthreads();
    if (tid < 128) {
        int wN = tid >> 5;
        int cc = tid & 31;
        float s = 0.f, q = 0.f;
#pragma unroll
        for (int w = 0; w < 4; ++w) {
            s += redS[(wN * 4 + w) * 32 + cc];
            q += redQ[(wN * 4 + w) * 32 + cc];
        }
        atomicAdd(&g_stats[tid], s);
        atomicAdd(&g_stats[D + tid], q);
    }
}

// ---------------------------------------------------------------------------
// Kernel 8: BN normalize; scale/shift recomputed per block. 2 float4/thread.
// ---------------------------------------------------------------------------
__global__ void k_norm(float4* __restrict__ out, int n4, int half4,
                       const float* __restrict__ gamma,
                       const float* __restrict__ beta, float invN) {
    __shared__ float s_sc[D], s_sh[D];
    int t = threadIdx.x;
    if (t < D) {
        float mean = g_stats[t] * invN;
        float var = g_stats[D + t] * invN - mean * mean;
        float sc = gamma[t] * rsqrtf(var + 1e-5f);
        s_sc[t] = sc;
        s_sh[t] = beta[t] - mean * sc;
    }
    __syncthreads();
    int i = blockIdx.x * blockDim.x + t;
#pragma unroll
    for (int r = 0; r < 2; ++r) {
        int idx = i + r * half4;
        if (idx < n4) {
            int c4 = (idx & 31) * 4;
            float4 sc = *reinterpret_cast<const float4*>(&s_sc[c4]);
            float4 sh = *reinterpret_cast<const float4*>(&s_sh[c4]);
            float4 v = out[idx];
            v.x = v.x * sc.x + sh.x;
            v.y = v.y * sc.y + sh.y;
            v.z = v.z * sc.z + sh.z;
            v.w = v.w * sc.w + sh.w;
            out[idx] = v;
        }
    }
}

// ---------------------------------------------------------------------------
extern "C" void kernel_launch(void* const* d_in, const int* in_sizes, int n_in,
                              void* d_out, int out_size) {
    const float* feat  = (const float*)d_in[0];
    const int*   ei    = (const int*)d_in[1];
    const float* W1    = (const float*)d_in[2];
    const float* b1    = (const float*)d_in[3];
    const float* W2    = (const float*)d_in[4];
    const float* b2    = (const float*)d_in[5];
    const float* gamma = (const float*)d_in[6];
    const float* beta  = (const float*)d_in[7];
    float* out = (float*)d_out;

    const int N = in_sizes[0] / D;     // 50000
    const int E = in_sizes[1] / 2;     // 600000
    const int n4 = N * D / 4;

    int sms = 148;
    cudaDeviceGetAttribute(&sms, cudaDevAttrMultiProcessorCount, 0);

    cudaFuncSetAttribute(k_fused, cudaFuncAttributeMaxDynamicSharedMemorySize, SMEM_FUSED);

    // CSR aggregation path (init also converts feat -> fp16)
    k_init<<<(n4 + 255) / 256, 256>>>(W1, W2, (const float4*)feat, n4);
    k_hist<<<((E >> 2) + 255) / 256, 256>>>(ei, E);
    k_bsum<<<NBLK, 1024>>>();
    k_off<<<NBLK, 1024>>>();
    k_reorder<<<((E >> 2) + 255) / 256, 256>>>(ei, E);
    k_agg<<<(N * 32 + 255) / 256, 256>>>(feat, N);

    // Fused MLP + BN stats
    k_fused<<<sms, 512, SMEM_FUSED>>>(b1, b2, out, N, (N + 63) / 64);

    // Normalize (finalize folded in)
    int half4 = (n4 + 1) / 2;
    k_norm<<<(half4 + 255) / 256, 256>>>((float4*)out, n4, half4,
                                         gamma, beta, 1.0f / (float)N);
}

// round 17
// speedup vs baseline: 1.1934x; 1.1934x over previous
#include <cuda_runtime.h>
#include <cuda_fp16.h>
#include <cstdint>

#define D 128
#define NMAX 50000
#define NPAD 50176          // 49 * 1024
#define EMAX 600000
#define NBLK 49             // scan blocks of 1024

// ---------------------------------------------------------------------------
// Scratch (__device__ globals per allocation rules)
// ---------------------------------------------------------------------------
__device__ __align__(16) __half g_hA[NPAD * D];    // (feat+agg) hi fp16; pad rows stay 0
__device__ __align__(16) __half g_hB[NPAD * D];    // (feat+agg) lo fp16
__device__ __align__(16) __half g_w1t[D * D];      // W1^T fp16 [col][k]
__device__ __align__(16) __half g_w2t[D * D];      // W2^T fp16
__device__ __align__(16) float  g_stats[2 * D];    // col sum/sumsq
__device__ int g_cnt[NPAD];        // per-dst edge counts
__device__ int g_off[NPAD + 1];    // CSR offsets
__device__ int g_cur[NPAD];        // scatter cursors
__device__ int g_srcs[EMAX];       // edge sources grouped by dst
__device__ int g_bsum[NBLK];       // per-block count sums

// ---------------------------------------------------------------------------
// PTX helpers (portable ISA only — tcgen05 unavailable on compute_103 target)
// ---------------------------------------------------------------------------
__device__ __forceinline__ void cp16(uint32_t dst, const void* src) {
    asm volatile("cp.async.cg.shared.global [%0], [%1], 16;" :: "r"(dst), "l"(src));
}
__device__ __forceinline__ void cp_commit() { asm volatile("cp.async.commit_group;"); }
template <int N>
__device__ __forceinline__ void cp_wait() {
    asm volatile("cp.async.wait_group %0;" :: "n"(N));
}
__device__ __forceinline__ uint32_t smem_u32(const void* p) {
    return (uint32_t)__cvta_generic_to_shared(p);
}
__device__ __forceinline__ void mma16816(float* c, const uint32_t* a, const uint32_t* b) {
    asm volatile(
        "mma.sync.aligned.m16n8k16.row.col.f32.f16.f16.f32 "
        "{%0,%1,%2,%3}, {%4,%5,%6,%7}, {%8,%9}, {%0,%1,%2,%3};"
        : "+f"(c[0]), "+f"(c[1]), "+f"(c[2]), "+f"(c[3])
        : "r"(a[0]), "r"(a[1]), "r"(a[2]), "r"(a[3]), "r"(b[0]), "r"(b[1]));
}
__device__ __forceinline__ void ldsm4(uint32_t* r, uint32_t addr) {
    asm volatile("ldmatrix.sync.aligned.m8n8.x4.shared.b16 {%0,%1,%2,%3}, [%4];"
                 : "=r"(r[0]), "=r"(r[1]), "=r"(r[2]), "=r"(r[3]) : "r"(addr));
}

// Padded row stride 136 halves (272 B): conflict-free ldmatrix/STS.
#define SH 136
#define TILE_B (128 * SH * 2)            // 34816 B : one weight tile (fp16)
#define TILE_A (64 * SH * 2)             // 17408 B : one A or Y tile (hi or lo)
#define OFF_A   (2 * TILE_B)             // 69632 : A hi/lo
#define OFF_Y   (OFF_A + 2 * TILE_A)     // 104448 : Y hi/lo
#define OFF_BIAS (OFF_Y + 2 * TILE_A)    // 139264
#define SMEM_FUSED (OFF_BIAS + 1024)     // 140288 B -> 1 CTA/SM

// ---------------------------------------------------------------------------
// Kernel 1: zero counts + stats, transpose weights -> fp16 (merged)
// ---------------------------------------------------------------------------
__global__ void k_init(const float* __restrict__ W1, const float* __restrict__ W2) {
    int i = blockIdx.x * blockDim.x + threadIdx.x;
    if (i < NPAD) g_cnt[i] = 0;
    if (i < 2 * D) g_stats[i] = 0.0f;
    if (i < D * D) {
        int k = i >> 7, c = i & 127;
        g_w1t[c * D + k] = __float2half_rn(W1[i]);
        g_w2t[c * D + k] = __float2half_rn(W2[i]);
    }
}

// ---------------------------------------------------------------------------
// Kernel 2: histogram of edge destinations — 4 edges/thread (MLP=4)
// ---------------------------------------------------------------------------
__global__ void k_hist(const int* __restrict__ ei, int E) {
    int i4 = blockIdx.x * blockDim.x + threadIdx.x;
    int e4 = E >> 2;
    if (i4 < e4) {
        int4 d = reinterpret_cast<const int4*>(ei + E)[i4];
        atomicAdd(&g_cnt[d.x], 1);
        atomicAdd(&g_cnt[d.y], 1);
        atomicAdd(&g_cnt[d.z], 1);
        atomicAdd(&g_cnt[d.w], 1);
    }
    int tail = e4 * 4 + i4;
    if (i4 < (E & 3)) atomicAdd(&g_cnt[ei[E + tail]], 1);
}

// ---------------------------------------------------------------------------
// Kernel 3: per-block (1024 counts) reduction -> g_bsum
// ---------------------------------------------------------------------------
__global__ void k_bsum() {
    __shared__ int s[32];
    int t = threadIdx.x;
    int v = g_cnt[blockIdx.x * 1024 + t];
#pragma unroll
    for (int off = 16; off > 0; off >>= 1) v += __shfl_xor_sync(0xFFFFFFFFu, v, off);
    if ((t & 31) == 0) s[t >> 5] = v;
    __syncthreads();
    if (t < 32) {
        int w = s[t];
#pragma unroll
        for (int off = 16; off > 0; off >>= 1) w += __shfl_xor_sync(0xFFFFFFFFu, w, off);
        if (t == 0) g_bsum[blockIdx.x] = w;
    }
}

// ---------------------------------------------------------------------------
// Kernel 4: per-block scan via two-level shfl; race-free block base (warp 1)
// ---------------------------------------------------------------------------
__global__ void k_off() {
    __shared__ int s_wsum[32];
    __shared__ int s_base;
    const int t = threadIdx.x;
    const int lane = t & 31;
    const int w = t >> 5;
    const int gi = blockIdx.x * 1024 + t;
    const int c = g_cnt[gi];

    int v = c;
#pragma unroll
    for (int off = 1; off < 32; off <<= 1) {
        int u = __shfl_up_sync(0xFFFFFFFFu, v, off);
        if (lane >= off) v += u;
    }
    if (lane == 31) s_wsum[w] = v;

    if (w == 1) {
        int b = 0;
        if (lane < blockIdx.x) b = g_bsum[lane];
        if (lane + 32 < blockIdx.x) b += g_bsum[lane + 32];
#pragma unroll
        for (int off = 16; off > 0; off >>= 1) b += __shfl_xor_sync(0xFFFFFFFFu, b, off);
        if (lane == 0) s_base = b;
    }
    __syncthreads();

    if (w == 0) {
        int x = s_wsum[lane];
#pragma unroll
        for (int off = 1; off < 32; off <<= 1) {
            int u = __shfl_up_sync(0xFFFFFFFFu, x, off);
            if (lane >= off) x += u;
        }
        s_wsum[lane] = x;
    }
    __syncthreads();

    const int base = s_base;
    const int incl = v + (w ? s_wsum[w - 1] : 0);
    const int excl = base + incl - c;
    g_off[gi] = excl;
    g_cur[gi] = excl;
    if (gi == NPAD - 1) g_off[NPAD] = base + s_wsum[31];
}

// ---------------------------------------------------------------------------
// Kernel 5: reorder edge sources into CSR order — 4 edges/thread (MLP=4)
// ---------------------------------------------------------------------------
__global__ void k_reorder(const int* __restrict__ ei, int E) {
    int i4 = blockIdx.x * blockDim.x + threadIdx.x;
    int e4 = E >> 2;
    if (i4 < e4) {
        int4 s = reinterpret_cast<const int4*>(ei)[i4];
        int4 d = reinterpret_cast<const int4*>(ei + E)[i4];
        int p0 = atomicAdd(&g_cur[d.x], 1);
        int p1 = atomicAdd(&g_cur[d.y], 1);
        int p2 = atomicAdd(&g_cur[d.z], 1);
        int p3 = atomicAdd(&g_cur[d.w], 1);
        g_srcs[p0] = s.x;
        g_srcs[p1] = s.y;
        g_srcs[p2] = s.z;
        g_srcs[p3] = s.w;
    }
    int tail = e4 * 4 + i4;
    if (i4 < (E & 3)) {
        int src = ei[tail];
        int dst = ei[E + tail];
        int pos = atomicAdd(&g_cur[dst], 1);
        g_srcs[pos] = src;
    }
}

// ---------------------------------------------------------------------------
// Kernel 6: gather-sum (exact f32) + self + fp16 hi/lo split (one warp/node)
// ---------------------------------------------------------------------------
__global__ void k_agg(const float* __restrict__ feat, int N) {
    int node = (blockIdx.x * blockDim.x + threadIdx.x) >> 5;
    int lane = threadIdx.x & 31;
    if (node >= N) return;
    int j = g_off[node];
    const int end = g_off[node + 1];
    const float4* f4 = reinterpret_cast<const float4*>(feat);
    float4 acc = f4[(size_t)node * 32 + lane];            // self term (GIN eps=0)
    for (; j + 3 < end; j += 4) {
        int s0 = g_srcs[j], s1 = g_srcs[j + 1], s2 = g_srcs[j + 2], s3 = g_srcs[j + 3];
        float4 v0 = f4[(size_t)s0 * 32 + lane];
        float4 v1 = f4[(size_t)s1 * 32 + lane];
        float4 v2 = f4[(size_t)s2 * 32 + lane];
        float4 v3 = f4[(size_t)s3 * 32 + lane];
        acc.x += v0.x; acc.y += v0.y; acc.z += v0.z; acc.w += v0.w;
        acc.x += v1.x; acc.y += v1.y; acc.z += v1.z; acc.w += v1.w;
        acc.x += v2.x; acc.y += v2.y; acc.z += v2.z; acc.w += v2.w;
        acc.x += v3.x; acc.y += v3.y; acc.z += v3.z; acc.w += v3.w;
    }
    for (; j < end; ++j) {
        int s0 = g_srcs[j];
        float4 v0 = f4[(size_t)s0 * 32 + lane];
        acc.x += v0.x; acc.y += v0.y; acc.z += v0.z; acc.w += v0.w;
    }
    // fp16 hi/lo split (hi+lo carries ~22 mantissa bits)
    __half2 h01 = __floats2half2_rn(acc.x, acc.y);
    __half2 h23 = __floats2half2_rn(acc.z, acc.w);
    __half2 l01 = __floats2half2_rn(acc.x - __half2float(h01.x),
                                    acc.y - __half2float(h01.y));
    __half2 l23 = __floats2half2_rn(acc.z - __half2float(h23.x),
                                    acc.w - __half2float(h23.y));
    uint2 hv, lv;
    hv.x = *reinterpret_cast<uint32_t*>(&h01);
    hv.y = *reinterpret_cast<uint32_t*>(&h23);
    lv.x = *reinterpret_cast<uint32_t*>(&l01);
    lv.y = *reinterpret_cast<uint32_t*>(&l23);
    reinterpret_cast<uint2*>(g_hA)[(size_t)node * 32 + lane] = hv;
    reinterpret_cast<uint2*>(g_hB)[(size_t)node * 32 + lane] = lv;
}

// ---------------------------------------------------------------------------
// Kernel 7: persistent fused MLP, 512 threads (16 warps), 64-row tiles.
// fp16 2-pass split GEMMs: AhW + AlW (W single fp16). A prefetched during
// epi1 + GEMM2. warpM = wid&3 (16-row quarters), warpN = wid>>2 (32-col).
// ---------------------------------------------------------------------------
__global__ __launch_bounds__(512, 1)
void k_fused(const float* __restrict__ b1, const float* __restrict__ b2,
             float* __restrict__ outF, int M, int nTiles) {
    extern __shared__ __align__(16) uint8_t smem[];
    const uint32_t sBase = smem_u32(smem);
    uint16_t* sYh = reinterpret_cast<uint16_t*>(smem + OFF_Y);
    uint16_t* sYl = reinterpret_cast<uint16_t*>(smem + OFF_Y + TILE_A);
    float* s_b1 = reinterpret_cast<float*>(smem + OFF_BIAS);
    float* s_b2 = s_b1 + D;

    const int tid = threadIdx.x;
    const int wid = tid >> 5;
    const int lane = tid & 31;
    const int g = lane >> 2;
    const int l4 = lane & 3;
    const int warpM = wid & 3;
    const int warpN = wid >> 2;

    if (tid < D) s_b1[tid] = b1[tid];
    else if (tid < 2 * D) s_b2[tid - D] = b2[tid - D];

    // ---- Load both weight tiles once (cp.async) ----
#pragma unroll
    for (int t = 0; t < 4; ++t) {
        int idx = tid + t * 512;            // 0..2047 = 128 rows x 16 chunks
        int row = idx >> 4;
        int kb = (idx & 15) * 16;
        uint32_t dOff = (uint32_t)(row * (SH * 2) + kb);
        size_t gOff = (size_t)row * 256 + kb;
        cp16(sBase + dOff,          (const uint8_t*)g_w1t + gOff);
        cp16(sBase + TILE_B + dOff, (const uint8_t*)g_w2t + gOff);
    }
    cp_commit();

    auto issueA = [&](int tile) {
        const int rowBase = tile * 64;
#pragma unroll
        for (int tt = 0; tt < 4; ++tt) {
            int idx = tid + tt * 512;
            int hl = idx >> 10;
            int row = (idx >> 4) & 63;
            int kb = (idx & 15) * 16;
            uint32_t dOff = (uint32_t)(OFF_A + hl * TILE_A + row * (SH * 2) + kb);
            size_t gOff = (size_t)(rowBase + row) * 256 + kb;
            cp16(sBase + dOff, (const uint8_t*)(hl ? g_hB : g_hA) + gOff);
        }
        cp_commit();
    };

    const int arow = warpM * 16 + (lane & 7) + ((lane >> 3) & 1) * 8;
    const uint32_t aOff = (uint32_t)((arow * SH + (lane >> 4) * 8) * 2);
    uint32_t bOff[2];
#pragma unroll
    for (int pr = 0; pr < 2; ++pr) {
        int brow = warpN * 32 + pr * 16 + (lane & 7) + (lane >> 4) * 8;
        int bkoff = ((lane >> 3) & 1) * 8;
        bOff[pr] = (uint32_t)((brow * SH + bkoff) * 2);
    }

    float cs[4][2], cq[4][2];
#pragma unroll
    for (int ni = 0; ni < 4; ++ni) {
        cs[ni][0] = cs[ni][1] = 0.f;
        cq[ni][0] = cq[ni][1] = 0.f;
    }

    float c[4][4];

    // 2-pass split GEMM: (aHi + aLo) x B, B single fp16 tile at bBase
    auto runGemm = [&](uint32_t aHi, uint32_t aLo, uint32_t bBase) {
#pragma unroll
        for (int ni = 0; ni < 4; ++ni)
#pragma unroll
            for (int e = 0; e < 4; ++e) c[ni][e] = 0.f;
#pragma unroll
        for (int pass = 0; pass < 2; ++pass) {
            const uint32_t aBase = pass ? aLo : aHi;
#pragma unroll
            for (int ks = 0; ks < 8; ++ks) {
                uint32_t a[4], b[2][4];
                ldsm4(a, aBase + aOff + ks * 32);
                ldsm4(b[0], bBase + bOff[0] + ks * 32);
                ldsm4(b[1], bBase + bOff[1] + ks * 32);
                mma16816(c[0], a, &b[0][0]);
                mma16816(c[1], a, &b[0][2]);
                mma16816(c[2], a, &b[1][0]);
                mma16816(c[3], a, &b[1][2]);
            }
        }
    };

    int t = blockIdx.x;
    if (t < nTiles) issueA(t);

    for (; t < nTiles; t += gridDim.x) {
        const int rowBase = t * 64;
        const int tNext = t + gridDim.x;

        cp_wait<0>();
        __syncthreads();

        runGemm(sBase + OFF_A, sBase + OFF_A + TILE_A, sBase);
        __syncthreads();

        if (tNext < nTiles) issueA(tNext);

        // ---- Epilogue 1: y1 = relu(c+b1), fp16 split -> sY ----
#pragma unroll
        for (int half = 0; half < 2; ++half) {
            const int lrow = warpM * 16 + g + half * 8;
#pragma unroll
            for (int ni = 0; ni < 4; ++ni) {
                const int col = warpN * 32 + ni * 8 + 2 * l4;
                float v0 = fmaxf(c[ni][half * 2 + 0] + s_b1[col], 0.f);
                float v1 = fmaxf(c[ni][half * 2 + 1] + s_b1[col + 1], 0.f);
                __half2 hh = __floats2half2_rn(v0, v1);
                __half2 ll = __floats2half2_rn(v0 - __half2float(hh.x),
                                               v1 - __half2float(hh.y));
                *reinterpret_cast<uint32_t*>(&sYh[lrow * SH + col]) =
                    *reinterpret_cast<uint32_t*>(&hh);
                *reinterpret_cast<uint32_t*>(&sYl[lrow * SH + col]) =
                    *reinterpret_cast<uint32_t*>(&ll);
            }
        }
        __syncthreads();

        runGemm(sBase + OFF_Y, sBase + OFF_Y + TILE_A, sBase + TILE_B);

        // ---- Epilogue 2: out = relu(c+b2) -> global + BN stats ----
#pragma unroll
        for (int half = 0; half < 2; ++half) {
            const int row = rowBase + warpM * 16 + g + half * 8;
            if (row < M) {
#pragma unroll
                for (int ni = 0; ni < 4; ++ni) {
                    const int col = warpN * 32 + ni * 8 + 2 * l4;
                    float v0 = fmaxf(c[ni][half * 2 + 0] + s_b2[col], 0.f);
                    float v1 = fmaxf(c[ni][half * 2 + 1] + s_b2[col + 1], 0.f);
                    float2 st; st.x = v0; st.y = v1;
                    *reinterpret_cast<float2*>(outF + (size_t)row * D + col) = st;
                    cs[ni][0] += v0; cs[ni][1] += v1;
                    cq[ni][0] += v0 * v0; cq[ni][1] += v1 * v1;
                }
            }
        }
    }

    // ---- Final BN stats reduction ----
#pragma unroll
    for (int off = 4; off < 32; off <<= 1) {
#pragma unroll
        for (int ni = 0; ni < 4; ++ni) {
#pragma unroll
            for (int e = 0; e < 2; ++e) {
                cs[ni][e] += __shfl_xor_sync(0xFFFFFFFFu, cs[ni][e], off);
                cq[ni][e] += __shfl_xor_sync(0xFFFFFFFFu, cq[ni][e], off);
            }
        }
    }
    __syncthreads();
    float* redS = reinterpret_cast<float*>(smem + OFF_A);    // [16][32]
    float* redQ = redS + 512;
    if (g == 0) {
#pragma unroll
        for (int ni = 0; ni < 4; ++ni) {
#pragma unroll
            for (int e = 0; e < 2; ++e) {
                int cc = ni * 8 + 2 * l4 + e;
                redS[wid * 32 + cc] = cs[ni][e];
                redQ[wid * 32 + cc] = cq[ni][e];
            }
        }
    }
    __syncthreads();
    if (tid < 128) {
        int wN = tid >> 5;
        int cc = tid & 31;
        float s = 0.f, q = 0.f;
#pragma unroll
        for (int w = 0; w < 4; ++w) {     // wid = wN*4 + warpM
            s += redS[(wN * 4 + w) * 32 + cc];
            q += redQ[(wN * 4 + w) * 32 + cc];
        }
        atomicAdd(&g_stats[tid], s);
        atomicAdd(&g_stats[D + tid], q);
    }
}

// ---------------------------------------------------------------------------
// Kernel 8: BN normalize; scale/shift recomputed per block. 2 float4/thread.
// ---------------------------------------------------------------------------
__global__ void k_norm(float4* __restrict__ out, int n4, int half4,
                       const float* __restrict__ gamma,
                       const float* __restrict__ beta, float invN) {
    __shared__ float s_sc[D], s_sh[D];
    int t = threadIdx.x;
    if (t < D) {
        float mean = g_stats[t] * invN;
        float var = g_stats[D + t] * invN - mean * mean;
        float sc = gamma[t] * rsqrtf(var + 1e-5f);
        s_sc[t] = sc;
        s_sh[t] = beta[t] - mean * sc;
    }
    __syncthreads();
    int i = blockIdx.x * blockDim.x + t;
#pragma unroll
    for (int r = 0; r < 2; ++r) {
        int idx = i + r * half4;
        if (idx < n4) {
            int c4 = (idx & 31) * 4;
            float4 sc = *reinterpret_cast<const float4*>(&s_sc[c4]);
            float4 sh = *reinterpret_cast<const float4*>(&s_sh[c4]);
            float4 v = out[idx];
            v.x = v.x * sc.x + sh.x;
            v.y = v.y * sc.y + sh.y;
            v.z = v.z * sc.z + sh.z;
            v.w = v.w * sc.w + sh.w;
            out[idx] = v;
        }
    }
}

// ---------------------------------------------------------------------------
extern "C" void kernel_launch(void* const* d_in, const int* in_sizes, int n_in,
                              void* d_out, int out_size) {
    const float* feat  = (const float*)d_in[0];
    const int*   ei    = (const int*)d_in[1];
    const float* W1    = (const float*)d_in[2];
    const float* b1    = (const float*)d_in[3];
    const float* W2    = (const float*)d_in[4];
    const float* b2    = (const float*)d_in[5];
    const float* gamma = (const float*)d_in[6];
    const float* beta  = (const float*)d_in[7];
    float* out = (float*)d_out;

    const int N = in_sizes[0] / D;     // 50000
    const int E = in_sizes[1] / 2;     // 600000
    const int n4 = N * D / 4;

    int sms = 148;
    cudaDeviceGetAttribute(&sms, cudaDevAttrMultiProcessorCount, 0);

    cudaFuncSetAttribute(k_fused, cudaFuncAttributeMaxDynamicSharedMemorySize, SMEM_FUSED);

    // CSR aggregation path
    k_init<<<(NPAD + 255) / 256, 256>>>(W1, W2);
    k_hist<<<((E >> 2) + 255) / 256, 256>>>(ei, E);
    k_bsum<<<NBLK, 1024>>>();
    k_off<<<NBLK, 1024>>>();
    k_reorder<<<((E >> 2) + 255) / 256, 256>>>(ei, E);
    k_agg<<<(N * 32 + 255) / 256, 256>>>(feat, N);

    // Fused MLP + BN stats
    k_fused<<<sms, 512, SMEM_FUSED>>>(b1, b2, out, N, (N + 63) / 64);

    // Normalize (finalize folded in)
    int half4 = (n4 + 1) / 2;
    k_norm<<<(half4 + 255) / 256, 256>>>((float4*)out, n4, half4,
                                         gamma, beta, 1.0f / (float)N);
}